// round 15
// baseline (speedup 1.0000x reference)
#include <cuda_runtime.h>
#include <cstdint>

// BFP quantize/dequantize: blocks of 16 contiguous fp32 share exponent
// e = floor(log2(max|x|)); q = clip(rint(x * 2^(7-e)), -128, 127); out = q * 2^(e-7).
//
// MLP=1 probe: one float4 per thread, 131,072 CTAs x 256 thr. Maximizes the
// CTA-replacement rate (the mechanism R12 showed supplies fresh loads to the
// memory queues). 4 consecutive lanes hold one 16-elem BFP block as float4s
// -> every warp LDG.128 covers a contiguous 512 B. Block max via 2 butterfly
// shuffles in the 4-lane group. Streaming hints (touch-once data).

__device__ __forceinline__ float4 bfp_qdq_vec(float4 v)
{
    float m = fmaxf(fmaxf(fabsf(v.x), fabsf(v.y)),
                    fmaxf(fabsf(v.z), fabsf(v.w)));
    m = fmaxf(m, __shfl_xor_sync(0xFFFFFFFFu, m, 1));
    m = fmaxf(m, __shfl_xor_sync(0xFFFFFFFFu, m, 2));

    float4 o;
    if (m > 0.0f) {
        // biased exponent of block max; floor(log2(m)) = eb - 127 for normals
        unsigned eb = __float_as_uint(m) >> 23;
        eb = eb < 8u ? 8u : eb;   // keep bit-built scales finite (denormal max)
        float scale = __uint_as_float((eb - 7u) << 23);   // 2^(e-7)
        float inv   = __uint_as_float((261u - eb) << 23); // 2^(7-e)

        o.x = fminf(127.0f, fmaxf(-128.0f, rintf(v.x * inv))) * scale;
        o.y = fminf(127.0f, fmaxf(-128.0f, rintf(v.y * inv))) * scale;
        o.z = fminf(127.0f, fmaxf(-128.0f, rintf(v.z * inv))) * scale;
        o.w = fminf(127.0f, fmaxf(-128.0f, rintf(v.w * inv))) * scale;
    } else {
        o.x = 0.0f; o.y = 0.0f; o.z = 0.0f; o.w = 0.0f;
    }
    return o;
}

__global__ void __launch_bounds__(256) bfp_qdq_kernel(
    const float4* __restrict__ in, float4* __restrict__ out, int n4)
{
    int i = blockIdx.x * blockDim.x + threadIdx.x;
    if (i < n4) {
        __stcs(&out[i], bfp_qdq_vec(__ldcs(&in[i])));
    }
}

extern "C" void kernel_launch(void* const* d_in, const int* in_sizes, int n_in,
                              void* d_out, int out_size)
{
    const float4* in  = (const float4*)d_in[0];
    float4*       out = (float4*)d_out;
    int n  = in_sizes[0];          // 134,217,728
    int n4 = n >> 2;               // 33,554,432 float4s

    const int threads = 256;
    int blocks = (n4 + threads - 1) / threads;     // 131,072 CTAs (exact)
    bfp_qdq_kernel<<<blocks, threads>>>(in, out, n4);
}

// round 17
// speedup vs baseline: 1.0541x; 1.0541x over previous
#include <cuda_runtime.h>
#include <cstdint>

// BFP quantize/dequantize: blocks of 16 contiguous fp32 share exponent
// e = floor(log2(max|x|)); q = clip(rint(x * 2^(7-e)), -128, 127); out = q * 2^(e-7).
//
// FINAL (R7 config, empirical optimum of the full launch-shape search):
// 256-thr CTAs, 2 front-batched float4s per thread (MLP=2), streaming cache
// hints, 24 regs, occ ~80%. 4 consecutive lanes hold one 16-elem BFP block
// as float4s -> every warp LDG.128 covers a contiguous 512 B. Block max via
// 2 butterfly shuffles in the 4-lane group.
//
// Measured map (kernel us / DRAM%):  MLP=1: 164.2/76.3  |  MLP=2: 152.4/81.8
// MLP=4+512thr: 153.5/81.3  |  persistent: 176.7/70.9  |  128thr: 153.2/81.5
// => ~6700 GB/s (83-84% of spec) is the chip's touch-once streaming ceiling;
// both per-warp MLP=2 AND the short-lived-CTA replacement stream are required.

__device__ __forceinline__ float4 bfp_qdq_vec(float4 v)
{
    float m = fmaxf(fmaxf(fabsf(v.x), fabsf(v.y)),
                    fmaxf(fabsf(v.z), fabsf(v.w)));
    m = fmaxf(m, __shfl_xor_sync(0xFFFFFFFFu, m, 1));
    m = fmaxf(m, __shfl_xor_sync(0xFFFFFFFFu, m, 2));

    float4 o;
    if (m > 0.0f) {
        // biased exponent of block max; floor(log2(m)) = eb - 127 for normals
        unsigned eb = __float_as_uint(m) >> 23;
        eb = eb < 8u ? 8u : eb;   // keep bit-built scales finite (denormal max)
        float scale = __uint_as_float((eb - 7u) << 23);   // 2^(e-7)
        float inv   = __uint_as_float((261u - eb) << 23); // 2^(7-e)

        o.x = fminf(127.0f, fmaxf(-128.0f, rintf(v.x * inv))) * scale;
        o.y = fminf(127.0f, fmaxf(-128.0f, rintf(v.y * inv))) * scale;
        o.z = fminf(127.0f, fmaxf(-128.0f, rintf(v.z * inv))) * scale;
        o.w = fminf(127.0f, fmaxf(-128.0f, rintf(v.w * inv))) * scale;
    } else {
        o.x = 0.0f; o.y = 0.0f; o.z = 0.0f; o.w = 0.0f;
    }
    return o;
}

__global__ void __launch_bounds__(256) bfp_qdq_kernel(
    const float4* __restrict__ in, float4* __restrict__ out, int n4)
{
    const int stride = gridDim.x * blockDim.x;
    const int i0 = blockIdx.x * blockDim.x + threadIdx.x;
    const int i1 = i0 + stride;

    if (i1 < n4) {
        // fast path (exact for the bench shape): 2 loads front-batched, MLP=2
        float4 v0 = __ldcs(&in[i0]);
        float4 v1 = __ldcs(&in[i1]);
        float4 o0 = bfp_qdq_vec(v0);
        float4 o1 = bfp_qdq_vec(v1);
        __stcs(&out[i0], o0);
        __stcs(&out[i1], o1);
    } else if (i0 < n4) {
        __stcs(&out[i0], bfp_qdq_vec(__ldcs(&in[i0])));
    }
}

extern "C" void kernel_launch(void* const* d_in, const int* in_sizes, int n_in,
                              void* d_out, int out_size)
{
    const float4* in  = (const float4*)d_in[0];
    float4*       out = (float4*)d_out;
    int n  = in_sizes[0];          // 134,217,728
    int n4 = n >> 2;               // 33,554,432 float4s

    const int threads = 256;
    const int per_cta = threads * 2;               // 2 float4s per thread
    int blocks = (n4 + per_cta - 1) / per_cta;     // 65,536 CTAs (exact)
    bfp_qdq_kernel<<<blocks, threads>>>(in, out, n4);
}